// round 11
// baseline (speedup 1.0000x reference)
#include <cuda_runtime.h>
#include <cstdint>

// SpherePool: out[bt, no, :] = max_k tensor[bt, index[no, k], :]
// B=2, T=8 (BT=16), N=40962, C=256 fp32, N_OUT=10242, K=7. Index = INT32.
//
// R6: 118.8us (occ 61.8, DRAM 75.4). R9: 114.8us (occ 84.0, DRAM 77.2) after
// launch_bounds(256,8)+__stcs. Traffic is compulsory (~707MB); remaining idle
// DRAM cycles attributed to per-thread idx-load serialization ahead of the
// gathers. This round: stage the block's 28 indices (4 rows x K=7) in smem,
// one bar.sync, then all 8 warps front-batch their 56 gather LDG.128s.
// Global LSU ops per block drop ~41%.

static constexpr int BT    = 16;
static constexpr int N_IN  = 40962;
static constexpr int C4    = 64;         // 256 floats / 4 = 64 float4 per row
static constexpr int N_OUT = 10242;
static constexpr int K     = 7;
static constexpr int ROWS_PER_BLOCK = 4; // 256 threads / 64 per row

__global__ __launch_bounds__(256, 8) void sphere_pool_kernel(
    const float4* __restrict__ x,        // [BT, N_IN, C4]
    const int* __restrict__ idx,         // [N_OUT, K] int32
    float4* __restrict__ out,            // [BT, N_OUT, C4]
    int total_rows)                      // BT * N_OUT
{
    __shared__ int s_idx[ROWS_PER_BLOCK * K];   // 28 ints

    int tid      = threadIdx.x;
    int row_base = blockIdx.x * ROWS_PER_BLOCK;

    // Stage indices: 28 threads, one global LDG.32 each.
    if (tid < ROWS_PER_BLOCK * K) {
        int r    = tid / K;              // row within block
        int k    = tid - r * K;
        int rest = row_base + r;
        if (rest < total_rows) {
            int no = rest % N_OUT;       // rows may straddle bt boundary
            s_idx[tid] = idx[no * K + k];
        }
    }
    __syncthreads();

    int r    = tid >> 6;                 // 0..3: row within block
    int c4   = tid & (C4 - 1);
    int rest = row_base + r;
    if (rest >= total_rows) return;
    int bt   = rest / N_OUT;

    const int* ip = s_idx + r * K;       // LDS broadcast, conflict-free
    int i0 = ip[0];
    int i1 = ip[1];
    int i2 = ip[2];
    int i3 = ip[3];
    int i4 = ip[4];
    int i5 = ip[5];
    int i6 = ip[6];

    // All offsets fit in int32 (max 16*40962*64 ~= 41.9M elements)
    const float4* base = x + bt * (N_IN * C4) + c4;

    // Issue all 7 gathers up-front: MLP=7 hides DRAM/L2 latency
    float4 v0 = __ldg(base + i0 * C4);
    float4 v1 = __ldg(base + i1 * C4);
    float4 v2 = __ldg(base + i2 * C4);
    float4 v3 = __ldg(base + i3 * C4);
    float4 v4 = __ldg(base + i4 * C4);
    float4 v5 = __ldg(base + i5 * C4);
    float4 v6 = __ldg(base + i6 * C4);

    float4 m;
    m.x = fmaxf(fmaxf(fmaxf(v0.x, v1.x), fmaxf(v2.x, v3.x)),
                fmaxf(fmaxf(v4.x, v5.x), v6.x));
    m.y = fmaxf(fmaxf(fmaxf(v0.y, v1.y), fmaxf(v2.y, v3.y)),
                fmaxf(fmaxf(v4.y, v5.y), v6.y));
    m.z = fmaxf(fmaxf(fmaxf(v0.z, v1.z), fmaxf(v2.z, v3.z)),
                fmaxf(fmaxf(v4.z, v5.z), v6.z));
    m.w = fmaxf(fmaxf(fmaxf(v0.w, v1.w), fmaxf(v2.w, v3.w)),
                fmaxf(fmaxf(v4.w, v5.w), v6.w));

    // Streaming store: output is never re-read; evict-first in L2.
    __stcs(&out[rest * C4 + c4], m);
}

extern "C" void kernel_launch(void* const* d_in, const int* in_sizes, int n_in,
                              void* d_out, int out_size)
{
    // Identify inputs by element count instead of assuming order:
    // tensor = 167,780,352 elems; index = 71,694 elems.
    int ti = 0, ii = 1;
    if (n_in >= 2 && in_sizes[0] < in_sizes[1]) { ti = 1; ii = 0; }

    const float4* x   = (const float4*)d_in[ti];  // tensor fp32
    const int*    idx = (const int*)d_in[ii];     // index int32
    float4*       out = (float4*)d_out;

    int total_rows = BT * N_OUT;                  // 163,872
    int grid = (total_rows + ROWS_PER_BLOCK - 1) / ROWS_PER_BLOCK;  // 40968
    sphere_pool_kernel<<<grid, 256>>>(x, idx, out, total_rows);
}

// round 13
// speedup vs baseline: 1.0480x; 1.0480x over previous
#include <cuda_runtime.h>
#include <cstdint>

// SpherePool: out[bt, no, :] = max_k tensor[bt, index[no, k], :]
// B=2, T=8 (BT=16), N=40962, C=256 fp32, N_OUT=10242, K=7. Index = INT32.
//
// History: R6 118.8us (occ 61.8, DRAM 75.4) -> R9 114.8us (occ 84.0, DRAM
// 77.2; launch_bounds(256,8) + __stcs) -> R11 smem idx staging REGRESSED to
// 120.3us (barrier convoy bunched DRAM demand; DRAM 72.8). Traffic is
// compulsory (~707MB = 554MB unique gathered rows + 168MB writes; L2 absorbs
// all index reuse). 77% DRAM on a random 1KB-row gather is the efficiency
// ceiling. This is the R9 design with the provably-dead bounds check removed
// (grid*block == total exactly: 40968*256 = 10,487,808).

static constexpr int BT    = 16;
static constexpr int N_IN  = 40962;
static constexpr int C4    = 64;         // 256 floats / 4 = 64 float4 per row
static constexpr int N_OUT = 10242;
static constexpr int K     = 7;

__global__ __launch_bounds__(256, 8) void sphere_pool_kernel(
    const float4* __restrict__ x,        // [BT, N_IN, C4]
    const int* __restrict__ idx,         // [N_OUT, K] int32
    float4* __restrict__ out)            // [BT, N_OUT, C4]
{
    int t = blockIdx.x * blockDim.x + threadIdx.x;

    int c4   = t & (C4 - 1);
    int rest = t >> 6;                   // / C4
    int no   = rest % N_OUT;
    int bt   = rest / N_OUT;

    // 7 indices: warp-uniform addresses -> 1 broadcast LDG per warp, L1-hit
    const int* ip = idx + no * K;
    int i0 = ip[0];
    int i1 = ip[1];
    int i2 = ip[2];
    int i3 = ip[3];
    int i4 = ip[4];
    int i5 = ip[5];
    int i6 = ip[6];

    // All offsets fit in int32 (max 16*40962*64 ~= 41.9M elements)
    const float4* base = x + bt * (N_IN * C4) + c4;

    // Issue all 7 gathers up-front: MLP=7 hides DRAM/L2 latency
    float4 v0 = __ldg(base + i0 * C4);
    float4 v1 = __ldg(base + i1 * C4);
    float4 v2 = __ldg(base + i2 * C4);
    float4 v3 = __ldg(base + i3 * C4);
    float4 v4 = __ldg(base + i4 * C4);
    float4 v5 = __ldg(base + i5 * C4);
    float4 v6 = __ldg(base + i6 * C4);

    float4 m;
    m.x = fmaxf(fmaxf(fmaxf(v0.x, v1.x), fmaxf(v2.x, v3.x)),
                fmaxf(fmaxf(v4.x, v5.x), v6.x));
    m.y = fmaxf(fmaxf(fmaxf(v0.y, v1.y), fmaxf(v2.y, v3.y)),
                fmaxf(fmaxf(v4.y, v5.y), v6.y));
    m.z = fmaxf(fmaxf(fmaxf(v0.z, v1.z), fmaxf(v2.z, v3.z)),
                fmaxf(fmaxf(v4.z, v5.z), v6.z));
    m.w = fmaxf(fmaxf(fmaxf(v0.w, v1.w), fmaxf(v2.w, v3.w)),
                fmaxf(fmaxf(v4.w, v5.w), v6.w));

    // Streaming store: output is never re-read; evict-first in L2.
    __stcs(&out[t], m);
}

extern "C" void kernel_launch(void* const* d_in, const int* in_sizes, int n_in,
                              void* d_out, int out_size)
{
    // Identify inputs by element count instead of assuming order:
    // tensor = 167,780,352 elems; index = 71,694 elems.
    int ti = 0, ii = 1;
    if (n_in >= 2 && in_sizes[0] < in_sizes[1]) { ti = 1; ii = 0; }

    const float4* x   = (const float4*)d_in[ti];  // tensor fp32
    const int*    idx = (const int*)d_in[ii];     // index int32
    float4*       out = (float4*)d_out;

    int total = BT * N_OUT * C4;                  // 10,487,808 = 40968 * 256
    sphere_pool_kernel<<<total / 256, 256>>>(x, idx, out);
}